// round 6
// baseline (speedup 1.0000x reference)
#include <cuda_runtime.h>

#define TPB 256
#define PPT 2
#define PPB (TPB * PPT)   // 512 points per block

// cov[n] = R(q_n) * diag(exp(2*scal_n)) * R(q_n)^T, q_n = normalize(rot_n)
__global__ void __launch_bounds__(TPB) gauss_cov_kernel(
    const float4* __restrict__ rot,    // [N,4]
    const float*  __restrict__ scal,   // [N,3]
    float*        __restrict__ out,    // [N,3,3]
    int n)
{
    __shared__ float s_scal[PPB * 3];   //  6144 B
    __shared__ float s_out [PPB * 9];   // 18432 B

    const int tid = threadIdx.x;
    const int base = blockIdx.x * PPB;
    const bool full = (base + PPB) <= n;

    // ---- stage scaling_raw: PPB*3 = 1536 floats = 384 float4 / block ----
    if (full) {
        const float4* sc4 = (const float4*)scal + (size_t)blockIdx.x * (PPB * 3 / 4);
        float4* s4 = (float4*)s_scal;
        s4[tid] = sc4[tid];                          // 256
        if (tid < PPB * 3 / 4 - TPB) s4[TPB + tid] = sc4[TPB + tid];  // 128
    } else {
        for (int k = tid; k < PPB * 3; k += TPB) {
            size_t g = (size_t)base * 3 + k;
            if (g < (size_t)n * 3) s_scal[k] = scal[g];
        }
    }

    // ---- hoist both quaternion loads (maximize MLP before sync/compute) ----
    const int i0 = base + tid;
    const int i1 = base + tid + TPB;
    float4 q0, q1;
    bool v0 = i0 < n, v1 = i1 < n;
    if (v0) q0 = rot[i0];
    if (v1) q1 = rot[i1];

    __syncthreads();

    #pragma unroll
    for (int p = 0; p < PPT; p++) {
        const bool valid = (p == 0) ? v0 : v1;
        if (!valid) continue;
        const float4 q = (p == 0) ? q0 : q1;
        const int local = tid + p * TPB;

        float inv = rsqrtf(q.x*q.x + q.y*q.y + q.z*q.z + q.w*q.w);
        float w = q.x * inv, x = q.y * inv, y = q.z * inv, z = q.w * inv;

        float r00 = 1.f - 2.f*(y*y + z*z);
        float r01 = 2.f*(x*y - w*z);
        float r02 = 2.f*(x*z + w*y);
        float r10 = 2.f*(x*y + w*z);
        float r11 = 1.f - 2.f*(x*x + z*z);
        float r12 = 2.f*(y*z - w*x);
        float r20 = 2.f*(x*z - w*y);
        float r21 = 2.f*(y*z + w*x);
        float r22 = 1.f - 2.f*(x*x + y*y);

        // s^2 = exp(2*scaling_raw); stride-3 smem reads: conflict-free
        float s0 = __expf(2.f * s_scal[3*local + 0]);
        float s1 = __expf(2.f * s_scal[3*local + 1]);
        float s2 = __expf(2.f * s_scal[3*local + 2]);

        float c00 = r00*r00*s0 + r01*r01*s1 + r02*r02*s2;
        float c01 = r00*r10*s0 + r01*r11*s1 + r02*r12*s2;
        float c02 = r00*r20*s0 + r01*r21*s1 + r02*r22*s2;
        float c11 = r10*r10*s0 + r11*r11*s1 + r12*r12*s2;
        float c12 = r10*r20*s0 + r11*r21*s1 + r12*r22*s2;
        float c22 = r20*r20*s0 + r21*r21*s1 + r22*r22*s2;

        // stride-9 smem writes: conflict-free
        float* so = s_out + local * 9;
        so[0] = c00; so[1] = c01; so[2] = c02;
        so[3] = c01; so[4] = c11; so[5] = c12;
        so[6] = c02; so[7] = c12; so[8] = c22;
    }
    __syncthreads();

    // ---- drain cov: PPB*9 = 4608 floats = 1152 float4 / block ----
    if (full) {
        float4* o4 = (float4*)out + (size_t)blockIdx.x * (PPB * 9 / 4);
        const float4* s4 = (const float4*)s_out;
        #pragma unroll
        for (int k = 0; k < 4; k++)
            o4[k * TPB + tid] = s4[k * TPB + tid];
        if (tid < PPB * 9 / 4 - 4 * TPB)                  // 128 tail
            o4[4 * TPB + tid] = s4[4 * TPB + tid];
    } else {
        for (int k = tid; k < PPB * 9; k += TPB) {
            size_t g = (size_t)base * 9 + k;
            if (g < (size_t)n * 9) out[g] = s_out[k];
        }
    }
}

extern "C" void kernel_launch(void* const* d_in, const int* in_sizes, int n_in,
                              void* d_out, int out_size)
{
    const float4* rot  = (const float4*)d_in[0];  // rotation_raw [N,4]
    const float*  scal = (const float*) d_in[1];  // scaling_raw  [N,3]
    float* out = (float*)d_out;                   // [N,3,3]
    int n = in_sizes[0] / 4;

    int blocks = (n + PPB - 1) / PPB;
    gauss_cov_kernel<<<blocks, TPB>>>(rot, scal, out, n);
}